// round 7
// baseline (speedup 1.0000x reference)
#include <cuda_runtime.h>
#include <math.h>

#define BTd 4
#define Ld 512
#define F1Dd 46
#define F2Dd 44
#define Cd 32
#define Kd 64
#define NBLKd 4
#define PWSTRIDE 109   // F2D + 2C + 1

#define NTOWER 128
#define NPAIR 8192

// Scratch (device globals: no allocation allowed; zero-initialized)
__device__ float g_x[BTd * Cd * Ld];
__device__ float g_y[BTd * Cd * Ld];
__device__ float g_eL[BTd * Ld * Kd];
__device__ float g_eR[BTd * Ld * Kd];
__device__ float g_pe[Ld * 32];   // pe_half: [l][0:16]=sin, [16:32]=cos
__device__ float g_sep[Ld];       // log(d+1)
__device__ unsigned g_cnt[16];    // grid-barrier slots (self-resetting)
__device__ unsigned g_done;       // tower-finished flag (self-resetting)
__device__ unsigned g_fin;        // pair-completion counter (self-resetting)

// ---------------------------------------------------------------------------
// f32x2 packed-FMA helpers (sm_100+)
// ---------------------------------------------------------------------------
static __device__ __forceinline__ unsigned long long pack2(float x, float y) {
    unsigned long long r;
    asm("mov.b64 %0, {%1,%2};" : "=l"(r) : "f"(x), "f"(y));
    return r;
}
static __device__ __forceinline__ void unpack2(unsigned long long v, float& x, float& y) {
    asm("mov.b64 {%0,%1}, %2;" : "=f"(x), "=f"(y) : "l"(v));
}
static __device__ __forceinline__ unsigned long long ffma2(unsigned long long a,
                                                           unsigned long long b,
                                                           unsigned long long c) {
    unsigned long long d;
    asm("fma.rn.f32x2 %0, %1, %2, %3;" : "=l"(d) : "l"(a), "l"(b), "l"(c));
    return d;
}

// ---------------------------------------------------------------------------
// software grid barrier among the NTOWER tower CTAs. Self-resetting.
// ---------------------------------------------------------------------------
static __device__ __forceinline__ void grid_bar(int b) {
    __syncthreads();
    if (threadIdx.x == 0) {
        __threadfence();
        unsigned t = atomicAdd(&g_cnt[b], 1u);
        if (t < NTOWER - 1u) {
            while (*((volatile unsigned*)&g_cnt[b]) < (unsigned)NTOWER) {}
        }
        __threadfence();
        unsigned u = atomicAdd(&g_cnt[b], 1u);
        if (u == 2u * NTOWER - 1u) {
            *((volatile unsigned*)&g_cnt[b]) = 0u;
        }
    }
    __syncthreads();
}

// block reduce over 128 threads: sums of (a,b) broadcast to all
static __device__ __forceinline__ float2 blockReduce2_128(float a, float b) {
    __shared__ float sa[4], sb[4], res[2];
    #pragma unroll
    for (int off = 16; off > 0; off >>= 1) {
        a += __shfl_down_sync(0xffffffffu, a, off);
        b += __shfl_down_sync(0xffffffffu, b, off);
    }
    int wid = threadIdx.x >> 5, lid = threadIdx.x & 31;
    if (lid == 0) { sa[wid] = a; sb[wid] = b; }
    __syncthreads();
    if (threadIdx.x == 0) {
        res[0] = (sa[0] + sa[1]) + (sa[2] + sa[3]);
        res[1] = (sb[0] + sb[1]) + (sb[2] + sb[3]);
    }
    __syncthreads();
    return make_float2(res[0], res[1]);
}

static __device__ __forceinline__ float conv_row(const float* __restrict__ xb,
                                                 const float* __restrict__ sw, int l) {
    float a0 = 0.f, a1 = 0.f, a2 = 0.f, a3 = 0.f;
    #pragma unroll
    for (int ci = 0; ci < Cd; ci += 4) {
        #pragma unroll
        for (int q = 0; q < 4; ++q) {
            const float* xr = xb + (ci + q) * Ld;
            float xm = (l > 0)      ? xr[l - 1] : 0.f;
            float x0 = xr[l];
            float xp = (l < Ld - 1) ? xr[l + 1] : 0.f;
            float s = sw[(ci + q) * 3 + 0] * xm + sw[(ci + q) * 3 + 1] * x0
                    + sw[(ci + q) * 3 + 2] * xp;
            if (q == 0) a0 += s; else if (q == 1) a1 += s;
            else if (q == 2) a2 += s; else a3 += s;
        }
    }
    return (a0 + a1) + (a2 + a3);
}

static __device__ __forceinline__ float elu1(float v) {
    return (v > 0.f) ? v : expm1f(v);
}

// ---------------------------------------------------------------------------
// shared-memory arena layout (overlaid tower/pair)
// ---------------------------------------------------------------------------
#define RTILE 128
#define RGS 360        // floats per rg: 44*8 + 8 pad
#define WGSTRIDE 89    // ulonglong2 per og (88 used + 1 pad)
#define SMEM_BYTES 35584

// pair offsets (bytes)
#define OFF_SA    0            // 5760 floats = 23040 B
#define OFF_SW4   23040        // 8*89*16 = 11392 B
#define OFF_SEL   34432        // 256 B
#define OFF_SWSEP 34688        // 256 B
#define OFF_SPEI  34944        // 128 B
#define OFF_SSEP  35072        // 512 B

__global__ __launch_bounds__(128, 4) void k_fused(
        const float* __restrict__ t1d, const float* __restrict__ t2d,
        const float* __restrict__ p1w, const float* __restrict__ p1b,
        const float* __restrict__ c1w, const float* __restrict__ c2w,
        const float* __restrict__ pw,  const float* __restrict__ pb,
        float* __restrict__ out) {
    __shared__ __align__(16) unsigned char sraw[SMEM_BYTES];
    const int tid = threadIdx.x;

    if (blockIdx.x < NTOWER) {
        // ================= TOWER path (128 CTAs x 128 threads) =============
        const int bid = blockIdx.x;
        float* shmem = (float*)sraw;

        // ---- tables (block 0) ----
        if (bid == 0) {
            const float c0 = -logf(10000.0f) / 32.0f;
            #pragma unroll
            for (int q = 0; q < 4; ++q) {
                int l = tid + 128 * q;
                g_sep[l] = logf((float)l + 1.0f);
                #pragma unroll
                for (int m = 0; m < 16; ++m) {
                    float div = expf((2.0f * m) * c0);
                    float a = (float)l * div;
                    g_pe[l * 32 + m]      = sinf(a);
                    g_pe[l * 32 + 16 + m] = cosf(a);
                }
            }
        }

        // ---- proj1d: block = (bt, l-chunk of 16) ----
        {
            const int bt = bid >> 5;
            const int l0 = (bid & 31) * 16;
            float* st  = shmem;            // [16][46]
            float* swp = shmem + 736;      // [32][46]
            const float* tb = t1d + ((size_t)(bt * Ld + l0)) * F1Dd;
            for (int idx = tid; idx < 16 * F1Dd; idx += 128) st[idx] = tb[idx];
            for (int idx = tid; idx < Cd * F1Dd; idx += 128) swp[idx] = p1w[idx];
            __syncthreads();
            #pragma unroll
            for (int q = 0; q < 4; ++q) {
                int oidx = tid + 128 * q;
                int c = oidx >> 4, ll = oidx & 15;
                float acc = p1b[c];
                #pragma unroll
                for (int f = 0; f < F1Dd; ++f)
                    acc += swp[c * F1Dd + f] * st[ll * F1Dd + f];
                g_x[(bt * Cd + c) * Ld + l0 + ll] = acc;
            }
        }
        grid_bar(0);

        // ---- conv tower: block = (co, bt), 4 l per thread ----
        {
            const int co = bid & 31;
            const int bt = bid >> 5;
            float* sw = shmem;  // [96]
            for (int blk = 0; blk < NBLKd; ++blk) {
                if (tid < Cd * 3) sw[tid] = c1w[((size_t)(blk * Cd + co)) * Cd * 3 + tid];
                __syncthreads();
                {
                    float acc[4]; float sA0 = 0.f, sB0 = 0.f;
                    #pragma unroll
                    for (int q = 0; q < 4; ++q) {
                        acc[q] = conv_row(g_x + bt * Cd * Ld, sw, tid + 128 * q);
                        sA0 += acc[q]; sB0 += acc[q] * acc[q];
                    }
                    float2 s = blockReduce2_128(sA0, sB0);
                    float m = s.x * (1.0f / Ld);
                    float var = s.y * (1.0f / Ld) - m * m;
                    float rstd = rsqrtf(var + 1e-5f);
                    #pragma unroll
                    for (int q = 0; q < 4; ++q)
                        g_y[(bt * Cd + co) * Ld + tid + 128 * q] = elu1((acc[q] - m) * rstd);
                }
                grid_bar(1 + 2 * blk);
                if (tid < Cd * 3) sw[tid] = c2w[((size_t)(blk * Cd + co)) * Cd * 3 + tid];
                __syncthreads();
                {
                    float acc[4]; float sA0 = 0.f, sB0 = 0.f;
                    #pragma unroll
                    for (int q = 0; q < 4; ++q) {
                        acc[q] = conv_row(g_y + bt * Cd * Ld, sw, tid + 128 * q);
                        sA0 += acc[q]; sB0 += acc[q] * acc[q];
                    }
                    float2 s = blockReduce2_128(sA0, sB0);
                    float m = s.x * (1.0f / Ld);
                    float var = s.y * (1.0f / Ld) - m * m;
                    float rstd = rsqrtf(var + 1e-5f);
                    #pragma unroll
                    for (int q = 0; q < 4; ++q) {
                        int idx = (bt * Cd + co) * Ld + tid + 128 * q;
                        float xo = g_x[idx] + (acc[q] - m) * rstd;
                        g_x[idx] = elu1(xo);
                    }
                }
                grid_bar(2 + 2 * blk);
            }
        }

        // ---- eL/eR: 131072 outputs, 1024 per CTA ----
        {
            float* sWl = shmem;              // [64][33]
            float* sWr = shmem + 64 * 33;    // [64][33]
            for (int idx = tid; idx < Kd * 64; idx += 128) {
                int o = idx >> 6, c2 = idx & 63;
                float v = pw[o * PWSTRIDE + F2Dd + c2];
                if (c2 < Cd) sWl[o * 33 + c2] = v;
                else         sWr[o * 33 + (c2 - Cd)] = v;
            }
            __syncthreads();
            #pragma unroll
            for (int q = 0; q < 8; ++q) {
                int T = bid * 1024 + q * 128 + tid;
                int o = T & 63;
                int lbt = T >> 6;
                int l = lbt & 511;
                int bt = lbt >> 9;
                float aL = pb[o], aR = 0.f;
                #pragma unroll
                for (int c = 0; c < Cd; ++c) {
                    float e = g_x[(bt * Cd + c) * Ld + l];
                    aL += sWl[o * 33 + c] * e;
                    aR += sWr[o * 33 + c] * e;
                }
                g_eL[((size_t)(bt * Ld + l)) * Kd + o] = aL;
                g_eR[((size_t)(bt * Ld + l)) * Kd + o] = aR;
            }
        }
        grid_bar(9);
        if (bid == 0 && tid == 0) {
            __threadfence();
            atomicExch(&g_done, 1u);
        }
        return;
    }

    // ==================== PAIR path (8192 CTAs x 128 threads) ==============
    float* sA            = (float*)(sraw + OFF_SA);
    ulonglong2* sW4      = (ulonglong2*)(sraw + OFF_SW4);
    float* sEL           = (float*)(sraw + OFF_SEL);
    float* sWsep         = (float*)(sraw + OFF_SWSEP);
    float* sPEi          = (float*)(sraw + OFF_SPEI);
    float* sSep          = (float*)(sraw + OFF_SSEP);

    const int bidx = blockIdx.x - NTOWER;
    const int bt = bidx >> 11;
    const int i  = (bidx >> 2) & 511;
    const int j0 = (bidx & 3) << 7;
    const size_t rowbase = ((size_t)(bt * Ld + i)) * Ld + j0;

    // stage t2d tile (streaming loads) + W quads + wsep (inputs only)
    {
        const float4* src = (const float4*)(t2d + rowbase * F2Dd);
        #pragma unroll
        for (int it = 0; it < 11; ++it) {
            int idx = tid + it * 128;             // 11*128 = 1408 exactly
            float4 v = __ldcs(src + idx);
            int r = idx / 11, kq = idx - r * 11;  // k = kq*4 .. kq*4+3
            int rg = r >> 3, rr = r & 7;
            float* d = sA + rg * RGS + kq * 32 + rr;
            d[0]  = v.x;
            d[8]  = v.y;
            d[16] = v.z;
            d[24] = v.w;
        }
    }
    for (int idx = tid; idx < 8 * WGSTRIDE; idx += 128) {
        int og = idx / WGSTRIDE, s = idx - og * WGSTRIDE;
        if (s < 88) {
            int k = s >> 1, h = s & 1;
            int o = og * 8 + h * 4;
            ((float4*)sW4)[idx] = make_float4(pw[(o + 0) * PWSTRIDE + k],
                                              pw[(o + 1) * PWSTRIDE + k],
                                              pw[(o + 2) * PWSTRIDE + k],
                                              pw[(o + 3) * PWSTRIDE + k]);
        }
    }
    if (tid < Kd) sWsep[tid] = pw[tid * PWSTRIDE + (PWSTRIDE - 1)];
    __syncthreads();

    const int og = tid & 7;
    const int rg = tid >> 3;             // 0..15, 8 rows each
    const float* aB = sA + rg * RGS;
    const ulonglong2* wB = sW4 + og * WGSTRIDE;

    unsigned long long acc[8][4];        // [rr][p], o = og*8 + 2p + e
    const unsigned long long z = pack2(0.f, 0.f);
    #pragma unroll
    for (int rr = 0; rr < 8; ++rr)
        #pragma unroll
        for (int p = 0; p < 4; ++p) acc[rr][p] = z;

    #pragma unroll 2
    for (int k = 0; k < F2Dd; ++k) {
        float4 av0 = *(const float4*)(aB + k * 8);       // rows 0..3
        float4 av1 = *(const float4*)(aB + k * 8 + 4);   // rows 4..7
        ulonglong2 q0 = wB[2 * k];        // w pairs p=0,1
        ulonglong2 q1 = wB[2 * k + 1];    // w pairs p=2,3
        unsigned long long a;
        a = pack2(av0.x, av0.x);
        acc[0][0] = ffma2(a, q0.x, acc[0][0]);
        acc[0][1] = ffma2(a, q0.y, acc[0][1]);
        acc[0][2] = ffma2(a, q1.x, acc[0][2]);
        acc[0][3] = ffma2(a, q1.y, acc[0][3]);
        a = pack2(av0.y, av0.y);
        acc[1][0] = ffma2(a, q0.x, acc[1][0]);
        acc[1][1] = ffma2(a, q0.y, acc[1][1]);
        acc[1][2] = ffma2(a, q1.x, acc[1][2]);
        acc[1][3] = ffma2(a, q1.y, acc[1][3]);
        a = pack2(av0.z, av0.z);
        acc[2][0] = ffma2(a, q0.x, acc[2][0]);
        acc[2][1] = ffma2(a, q0.y, acc[2][1]);
        acc[2][2] = ffma2(a, q1.x, acc[2][2]);
        acc[2][3] = ffma2(a, q1.y, acc[2][3]);
        a = pack2(av0.w, av0.w);
        acc[3][0] = ffma2(a, q0.x, acc[3][0]);
        acc[3][1] = ffma2(a, q0.y, acc[3][1]);
        acc[3][2] = ffma2(a, q1.x, acc[3][2]);
        acc[3][3] = ffma2(a, q1.y, acc[3][3]);
        a = pack2(av1.x, av1.x);
        acc[4][0] = ffma2(a, q0.x, acc[4][0]);
        acc[4][1] = ffma2(a, q0.y, acc[4][1]);
        acc[4][2] = ffma2(a, q1.x, acc[4][2]);
        acc[4][3] = ffma2(a, q1.y, acc[4][3]);
        a = pack2(av1.y, av1.y);
        acc[5][0] = ffma2(a, q0.x, acc[5][0]);
        acc[5][1] = ffma2(a, q0.y, acc[5][1]);
        acc[5][2] = ffma2(a, q1.x, acc[5][2]);
        acc[5][3] = ffma2(a, q1.y, acc[5][3]);
        a = pack2(av1.z, av1.z);
        acc[6][0] = ffma2(a, q0.x, acc[6][0]);
        acc[6][1] = ffma2(a, q0.y, acc[6][1]);
        acc[6][2] = ffma2(a, q1.x, acc[6][2]);
        acc[6][3] = ffma2(a, q1.y, acc[6][3]);
        a = pack2(av1.w, av1.w);
        acc[7][0] = ffma2(a, q0.x, acc[7][0]);
        acc[7][1] = ffma2(a, q0.y, acc[7][1]);
        acc[7][2] = ffma2(a, q1.x, acc[7][2]);
        acc[7][3] = ffma2(a, q1.y, acc[7][3]);
    }

    // ---- wait for tower outputs, then stage them ----
    if (tid == 0) {
        while (*((volatile unsigned*)&g_done) == 0u) { __nanosleep(128); }
        __threadfence();   // acquire + L1 invalidate
    }
    __syncthreads();
    if (tid < Kd) sEL[tid] = g_eL[((size_t)(bt * Ld + i)) * Kd + tid];
    if (tid < 32) sPEi[tid] = g_pe[i * 32 + tid];
    { int j = j0 + tid; sSep[tid] = g_sep[abs(i - j)]; }
    __syncthreads();

    // epilogue: acc[rr][p] -> v[2p], v[2p+1] with o = og*8 + 2p + e
    const int ob = og * 8;
    float base[8], ws[8];
    {
        float4 e0 = *(const float4*)(sEL + ob);
        float4 e1 = *(const float4*)(sEL + ob + 4);
        base[0]=e0.x; base[1]=e0.y; base[2]=e0.z; base[3]=e0.w;
        base[4]=e1.x; base[5]=e1.y; base[6]=e1.z; base[7]=e1.w;
        float4 w0 = *(const float4*)(sWsep + ob);
        float4 w1 = *(const float4*)(sWsep + ob + 4);
        ws[0]=w0.x; ws[1]=w0.y; ws[2]=w0.z; ws[3]=w0.w;
        ws[4]=w1.x; ws[5]=w1.y; ws[6]=w1.z; ws[7]=w1.w;
        if (bt == 0 && ob < 32) {
            #pragma unroll
            for (int t = 0; t < 8; ++t) base[t] += sPEi[ob + t];
        }
    }
    const bool addpeJ = (bt == 0) && (ob >= 32);
    const int jl0 = rg * 8;
    #pragma unroll
    for (int rr = 0; rr < 8; ++rr) {
        const int jl = jl0 + rr;
        const int j = j0 + jl;
        const float sep = sSep[jl];
        const float* eRp = g_eR + ((size_t)(bt * Ld + j)) * Kd + ob;
        float4 r0 = *(const float4*)(eRp);
        float4 r1 = *(const float4*)(eRp + 4);
        float v[8];
        unpack2(acc[rr][0], v[0], v[1]);
        unpack2(acc[rr][1], v[2], v[3]);
        unpack2(acc[rr][2], v[4], v[5]);
        unpack2(acc[rr][3], v[6], v[7]);
        v[0] += base[0] + r0.x + sep * ws[0];
        v[1] += base[1] + r0.y + sep * ws[1];
        v[2] += base[2] + r0.z + sep * ws[2];
        v[3] += base[3] + r0.w + sep * ws[3];
        v[4] += base[4] + r1.x + sep * ws[4];
        v[5] += base[5] + r1.y + sep * ws[5];
        v[6] += base[6] + r1.z + sep * ws[6];
        v[7] += base[7] + r1.w + sep * ws[7];
        if (addpeJ) {
            const float* pj = g_pe + j * 32 + (ob - 32);
            float4 p0 = *(const float4*)(pj);
            float4 p1 = *(const float4*)(pj + 4);
            v[0] += p0.x; v[1] += p0.y; v[2] += p0.z; v[3] += p0.w;
            v[4] += p1.x; v[5] += p1.y; v[6] += p1.z; v[7] += p1.w;
        }
        float4* dst = (float4*)(out + (rowbase + jl) * Kd + ob);
        __stcs(dst,     make_float4(v[0], v[1], v[2], v[3]));
        __stcs(dst + 1, make_float4(v[4], v[5], v[6], v[7]));
    }

    // ---- self-reset of flag for graph replays (last pair CTA) ----
    __syncthreads();
    if (tid == 0) {
        unsigned f = atomicAdd(&g_fin, 1u);
        if (f == (unsigned)(NPAIR - 1)) {
            g_done = 0u;
            g_fin = 0u;
            __threadfence();
        }
    }
}

// ---------------------------------------------------------------------------
extern "C" void kernel_launch(void* const* d_in, const int* in_sizes, int n_in,
                              void* d_out, int out_size) {
    const float* t1d = (const float*)d_in[0];
    const float* t2d = (const float*)d_in[1];
    const float* p1w = (const float*)d_in[2];
    const float* p1b = (const float*)d_in[3];
    const float* c1w = (const float*)d_in[4];
    const float* c2w = (const float*)d_in[5];
    const float* pw  = (const float*)d_in[6];
    const float* pb  = (const float*)d_in[7];
    float* out = (float*)d_out;
    (void)in_sizes; (void)n_in; (void)out_size;

    k_fused<<<NTOWER + NPAIR, 128>>>(t1d, t2d, p1w, p1b, c1w, c2w, pw, pb, out);
}

// round 10
// speedup vs baseline: 2.2057x; 2.2057x over previous
#include <cuda_runtime.h>
#include <cuda_bf16.h>
#include <math.h>
#include <stdint.h>

#define BTd 4
#define Ld 512
#define F1Dd 46
#define F2Dd 44
#define Cd 32
#define Kd 64
#define NBLKd 4
#define PWSTRIDE 109   // F2D + 2C + 1
#define KP 48          // K padded for MMA (3 chunks of 16)

// Scratch (device globals; zero-initialized)
__device__ float g_x[BTd * Cd * Ld];
__device__ float g_y[BTd * Cd * Ld];
__device__ float g_eL[BTd * Ld * Kd];
__device__ float g_eR[BTd * Ld * Kd];
__device__ float g_pe[Ld * 32];
__device__ float g_sep[Ld];
__device__ unsigned g_cnt[16];
// W hi/lo bf16 images, [64][KP] row-major (k >= F2D zero)
__device__ __align__(16) unsigned short g_Wh[64 * KP];
__device__ __align__(16) unsigned short g_Wl[64 * KP];

// ---------------------------------------------------------------------------
// tower kernel (proven R6 version + W-image precompute)
// ---------------------------------------------------------------------------
#define NB_TOWER 128u
static __device__ __forceinline__ void grid_bar(int b) {
    __syncthreads();
    if (threadIdx.x == 0) {
        __threadfence();
        unsigned t = atomicAdd(&g_cnt[b], 1u);
        if (t < NB_TOWER - 1u) {
            while (*((volatile unsigned*)&g_cnt[b]) < NB_TOWER) {}
        }
        __threadfence();
        unsigned u = atomicAdd(&g_cnt[b], 1u);
        if (u == 2u * NB_TOWER - 1u) *((volatile unsigned*)&g_cnt[b]) = 0u;
    }
    __syncthreads();
}

static __device__ __forceinline__ float2 blockReduce2(float a, float b) {
    __shared__ float sa[16], sb[16], res[2];
    #pragma unroll
    for (int off = 16; off > 0; off >>= 1) {
        a += __shfl_down_sync(0xffffffffu, a, off);
        b += __shfl_down_sync(0xffffffffu, b, off);
    }
    int wid = threadIdx.x >> 5, lid = threadIdx.x & 31;
    if (lid == 0) { sa[wid] = a; sb[wid] = b; }
    __syncthreads();
    if (threadIdx.x == 0) {
        float ta = 0.f, tb = 0.f;
        #pragma unroll
        for (int i = 0; i < 16; ++i) { ta += sa[i]; tb += sb[i]; }
        res[0] = ta; res[1] = tb;
    }
    __syncthreads();
    return make_float2(res[0], res[1]);
}

static __device__ __forceinline__ float conv_row(const float* __restrict__ xb,
                                                 const float* __restrict__ sw, int l) {
    float a0 = 0.f, a1 = 0.f, a2 = 0.f, a3 = 0.f;
    #pragma unroll
    for (int ci = 0; ci < Cd; ci += 4) {
        #pragma unroll
        for (int q = 0; q < 4; ++q) {
            const float* xr = xb + (ci + q) * Ld;
            float xm = (l > 0)      ? xr[l - 1] : 0.f;
            float x0 = xr[l];
            float xp = (l < Ld - 1) ? xr[l + 1] : 0.f;
            float s = sw[(ci + q) * 3 + 0] * xm + sw[(ci + q) * 3 + 1] * x0
                    + sw[(ci + q) * 3 + 2] * xp;
            if (q == 0) a0 += s; else if (q == 1) a1 += s;
            else if (q == 2) a2 += s; else a3 += s;
        }
    }
    return (a0 + a1) + (a2 + a3);
}

__global__ __launch_bounds__(512) void k_tower(const float* __restrict__ t1d,
                                               const float* __restrict__ p1w,
                                               const float* __restrict__ p1b,
                                               const float* __restrict__ c1w,
                                               const float* __restrict__ c2w,
                                               const float* __restrict__ pw,
                                               const float* __restrict__ pb) {
    __shared__ float shmem[4352];
    const int bid = blockIdx.x;
    const int tid = threadIdx.x;

    if (bid == 0) {   // tables
        int l = tid;
        g_sep[l] = logf((float)l + 1.0f);
        const float c0 = -logf(10000.0f) / 32.0f;
        #pragma unroll
        for (int m = 0; m < 16; ++m) {
            float div = expf((2.0f * m) * c0);
            float a = (float)l * div;
            g_pe[l * 32 + m]      = sinf(a);
            g_pe[l * 32 + 16 + m] = cosf(a);
        }
    }
    if (bid == 127) { // W hi/lo bf16 images [64][KP]
        for (int idx = tid; idx < 64 * KP; idx += 512) {
            int n = idx / KP, k = idx - n * KP;
            float v = (k < F2Dd) ? pw[n * PWSTRIDE + k] : 0.f;
            __nv_bfloat16 h = __float2bfloat16(v);
            float lo = v - __bfloat162float(h);
            g_Wh[idx] = __bfloat16_as_ushort(h);
            g_Wl[idx] = __bfloat16_as_ushort(__float2bfloat16(lo));
        }
    }

    // proj1d
    {
        const int bt = bid >> 5;
        const int l0 = (bid & 31) * 16;
        float* st  = shmem;
        float* swp = shmem + 736;
        const float* tb = t1d + ((size_t)(bt * Ld + l0)) * F1Dd;
        for (int idx = tid; idx < 16 * F1Dd; idx += 512) st[idx] = tb[idx];
        for (int idx = tid; idx < Cd * F1Dd; idx += 512) swp[idx] = p1w[idx];
        __syncthreads();
        const int c = tid >> 4, ll = tid & 15;
        float acc = p1b[c];
        #pragma unroll
        for (int f = 0; f < F1Dd; ++f) acc += swp[c * F1Dd + f] * st[ll * F1Dd + f];
        g_x[(bt * Cd + c) * Ld + l0 + ll] = acc;
    }
    grid_bar(0);

    // conv tower
    {
        const int co = bid & 31;
        const int bt = bid >> 5;
        const int l = tid;
        float* sw = shmem;
        for (int blk = 0; blk < NBLKd; ++blk) {
            if (tid < Cd * 3) sw[tid] = c1w[((size_t)(blk * Cd + co)) * Cd * 3 + tid];
            __syncthreads();
            {
                float acc = conv_row(g_x + bt * Cd * Ld, sw, l);
                float2 s = blockReduce2(acc, acc * acc);
                float m = s.x * (1.0f / Ld);
                float var = s.y * (1.0f / Ld) - m * m;
                float v = (acc - m) * rsqrtf(var + 1e-5f);
                g_y[(bt * Cd + co) * Ld + l] = (v > 0.f) ? v : expm1f(v);
            }
            grid_bar(1 + 2 * blk);
            if (tid < Cd * 3) sw[tid] = c2w[((size_t)(blk * Cd + co)) * Cd * 3 + tid];
            __syncthreads();
            {
                float acc = conv_row(g_y + bt * Cd * Ld, sw, l);
                float2 s = blockReduce2(acc, acc * acc);
                float m = s.x * (1.0f / Ld);
                float var = s.y * (1.0f / Ld) - m * m;
                float v = (acc - m) * rsqrtf(var + 1e-5f);
                int idx = (bt * Cd + co) * Ld + l;
                float xo = g_x[idx] + v;
                g_x[idx] = (xo > 0.f) ? xo : expm1f(xo);
            }
            grid_bar(2 + 2 * blk);
        }
    }

    // eL/eR
    {
        float* sWl = shmem;
        float* sWr = shmem + 64 * 33;
        for (int idx = tid; idx < Kd * 64; idx += 512) {
            int o = idx >> 6, c2 = idx & 63;
            float v = pw[o * PWSTRIDE + F2Dd + c2];
            if (c2 < Cd) sWl[o * 33 + c2] = v;
            else         sWr[o * 33 + (c2 - Cd)] = v;
        }
        __syncthreads();
        const int T = bid * 512 + tid;
        const int o = T & 63;
        const int lbt = T >> 6;
        const int l = lbt & 511;
        const int bh = lbt >> 9;
        const float bias = pb[o];
        #pragma unroll
        for (int bt2 = 0; bt2 < 2; ++bt2) {
            const int bt = bh * 2 + bt2;
            float aL = bias, aR = 0.f;
            #pragma unroll
            for (int c = 0; c < Cd; ++c) {
                float e = g_x[(bt * Cd + c) * Ld + l];
                aL += sWl[o * 33 + c] * e;
                aR += sWr[o * 33 + c] * e;
            }
            g_eL[((size_t)(bt * Ld + l)) * Kd + o] = aL;
            g_eR[((size_t)(bt * Ld + l)) * Kd + o] = aR;
        }
    }
}

// ---------------------------------------------------------------------------
// pair kernel: warp-level mma.sync bf16 hi/lo GEMM (M=128 N=64 K=48)
// ---------------------------------------------------------------------------
static __device__ __forceinline__ uint32_t smem_u32(const void* p) {
    uint32_t a;
    asm("{ .reg .u64 t; cvta.to.shared.u64 t, %1; cvt.u32.u64 %0, t; }" : "=r"(a) : "l"(p));
    return a;
}
static __device__ __forceinline__ uint32_t cvt_bf16x2(float lo, float hi) {
    uint32_t r;  // d.lo = bf16(lo arg), d.hi = bf16(hi arg)
    asm("cvt.rn.satfinite.bf16x2.f32 %0, %1, %2;" : "=r"(r) : "f"(hi), "f"(lo));
    return r;
}
static __device__ __forceinline__ void ldm_x4(uint32_t* r, uint32_t addr) {
    asm volatile("ldmatrix.sync.aligned.m8n8.x4.shared.b16 {%0,%1,%2,%3}, [%4];"
                 : "=r"(r[0]), "=r"(r[1]), "=r"(r[2]), "=r"(r[3]) : "r"(addr));
}
static __device__ __forceinline__ void mma_bf16(float* d, const uint32_t* a,
                                                const uint32_t* b) {
    asm volatile(
        "mma.sync.aligned.m16n8k16.row.col.f32.bf16.bf16.f32 "
        "{%0,%1,%2,%3}, {%4,%5,%6,%7}, {%8,%9}, {%0,%1,%2,%3};"
        : "+f"(d[0]), "+f"(d[1]), "+f"(d[2]), "+f"(d[3])
        : "r"(a[0]), "r"(a[1]), "r"(a[2]), "r"(a[3]), "r"(b[0]), "r"(b[1]));
}

// smem layout (bytes). Row stride 112 B (= 56 bf16; 28 words, conflict-free).
#define ARS 112
#define PA_HI 0                      // 128*112 = 14336
#define PA_LO 14336                  // 14336 -> 28672
#define PB_HI 28672                  // 64*112 = 7168 -> 35840
#define PB_LO 35840                  // 7168 -> 43008
#define PSB   43008                  // 64 f32
#define PSW   43264                  // 64 f32
#define PSS   43520                  // 128 f32 -> 44032
#define DSMEM 44032
#define SOUTS 68                     // sOut stride (words); overlays PA/PB region

__global__ __launch_bounds__(128) void k_pair(const float* __restrict__ t2d,
                                              const float* __restrict__ pw,
                                              float* __restrict__ out) {
    extern __shared__ __align__(16) unsigned char dsm[];
    const int tid = threadIdx.x;
    const int wid = tid >> 5;
    const int lid = tid & 31;
    const uint32_t sbase = smem_u32(dsm);

    const int bidx = blockIdx.x;
    const int bt = bidx >> 11;
    const int i  = (bidx >> 2) & 511;
    const int j0 = (bidx & 3) << 7;
    const size_t rowbase = ((size_t)(bt * Ld + i)) * Ld + j0;

    // ---- stage W images [64][KP] -> strided smem rows (6 uint4 per row) ----
    {
        const uint4* wh = (const uint4*)g_Wh;
        const uint4* wl = (const uint4*)g_Wl;
        #pragma unroll
        for (int q = 0; q < 3; ++q) {
            int idx = tid + q * 128;            // 384 = 64 rows * 6
            int r = idx / 6, c = idx - r * 6;
            *(uint4*)(dsm + PB_HI + r * ARS + c * 16) = wh[idx];
            *(uint4*)(dsm + PB_LO + r * ARS + c * 16) = wl[idx];
        }
    }
    // ---- small tables ----
    if (tid < Kd) {
        float b = g_eL[((size_t)(bt * Ld + i)) * Kd + tid];
        if (bt == 0 && tid < 32) b += g_pe[i * 32 + tid];
        ((float*)(dsm + PSB))[tid] = b;
        ((float*)(dsm + PSW))[tid] = pw[tid * PWSTRIDE + (PWSTRIDE - 1)];
    }
    { int j = j0 + tid; ((float*)(dsm + PSS))[tid] = g_sep[abs(i - j)]; }

    // ---- convert t2d tile -> bf16 hi/lo [128][KP] (stride ARS) ----
    {
        const float4* src = (const float4*)(t2d + rowbase * F2Dd);
        #pragma unroll
        for (int it = 0; it < 11; ++it) {
            int idx = tid + it * 128;             // 1408 exactly
            float4 x = __ldcs(src + idx);
            int r = idx / 11, kq = idx - r * 11;
            uint32_t h0 = cvt_bf16x2(x.x, x.y);
            uint32_t h1 = cvt_bf16x2(x.z, x.w);
            float f00 = __uint_as_float(h0 << 16);
            float f01 = __uint_as_float(h0 & 0xFFFF0000u);
            float f10 = __uint_as_float(h1 << 16);
            float f11 = __uint_as_float(h1 & 0xFFFF0000u);
            uint32_t l0 = cvt_bf16x2(x.x - f00, x.y - f01);
            uint32_t l1 = cvt_bf16x2(x.z - f10, x.w - f11);
            *(uint2*)(dsm + PA_HI + r * ARS + kq * 8) = make_uint2(h0, h1);
            *(uint2*)(dsm + PA_LO + r * ARS + kq * 8) = make_uint2(l0, l1);
        }
        // zero pad k = 44..47 (bytes 88..95 of each row)
        *(uint2*)(dsm + PA_HI + tid * ARS + 88) = make_uint2(0u, 0u);
        *(uint2*)(dsm + PA_LO + tid * ARS + 88) = make_uint2(0u, 0u);
    }
    __syncthreads();

    // ---- MMA: warp w owns rows w*32..w*32+31 (2 m16-tiles) x 64 cols ----
    float acc[2][8][4];
    #pragma unroll
    for (int mt = 0; mt < 2; ++mt)
        #pragma unroll
        for (int nt = 0; nt < 8; ++nt)
            #pragma unroll
            for (int e = 0; e < 4; ++e) acc[mt][nt][e] = 0.f;

    // ldmatrix lane addresses
    //   A (.x4, m16k16 at (mt, kc)): row = w*32 + mt*16 + lid%16, +16B if lid>=16
    //   B (.x4, two n8-tiles at (nt2, kc)): rows nt2*16 + (lid%8) + 8*(lid>=16),
    //                                       +16B if (lid/8) odd
    const uint32_t aRow = (uint32_t)(wid * 32 + (lid & 15)) * ARS + (uint32_t)((lid >> 4) * 16);
    const uint32_t bRow = (uint32_t)((lid & 7) + ((lid >> 4) << 3)) * ARS
                        + (uint32_t)(((lid >> 3) & 1) * 16);

    #pragma unroll
    for (int kc = 0; kc < 3; ++kc) {
        uint32_t Ah[2][4], Al[2][4];
        ldm_x4(Ah[0], sbase + PA_HI + aRow + kc * 32);
        ldm_x4(Ah[1], sbase + PA_HI + aRow + 16 * ARS + kc * 32);
        ldm_x4(Al[0], sbase + PA_LO + aRow + kc * 32);
        ldm_x4(Al[1], sbase + PA_LO + aRow + 16 * ARS + kc * 32);
        uint32_t Bh[8][2], Bl[8][2];
        #pragma unroll
        for (int nt2 = 0; nt2 < 4; ++nt2) {
            uint32_t rh[4], rl[4];
            ldm_x4(rh, sbase + PB_HI + bRow + (uint32_t)(nt2 * 16) * ARS + kc * 32);
            ldm_x4(rl, sbase + PB_LO + bRow + (uint32_t)(nt2 * 16) * ARS + kc * 32);
            Bh[nt2 * 2][0] = rh[0]; Bh[nt2 * 2][1] = rh[1];
            Bh[nt2 * 2 + 1][0] = rh[2]; Bh[nt2 * 2 + 1][1] = rh[3];
            Bl[nt2 * 2][0] = rl[0]; Bl[nt2 * 2][1] = rl[1];
            Bl[nt2 * 2 + 1][0] = rl[2]; Bl[nt2 * 2 + 1][1] = rl[3];
        }
        #pragma unroll
        for (int mt = 0; mt < 2; ++mt)
            #pragma unroll
            for (int nt = 0; nt < 8; ++nt) {
                mma_bf16(acc[mt][nt], Ah[mt], Bh[nt]);
                mma_bf16(acc[mt][nt], Al[mt], Bh[nt]);
                mma_bf16(acc[mt][nt], Ah[mt], Bl[nt]);
            }
    }
    __syncthreads();   // A/B smem dead -> reuse as sOut

    // ---- D frags -> sOut[row][o] (stride SOUTS) ----
    {
        float* sOut = (float*)dsm;
        #pragma unroll
        for (int mt = 0; mt < 2; ++mt) {
            const int r0 = wid * 32 + mt * 16 + (lid >> 2);
            #pragma unroll
            for (int nt = 0; nt < 8; ++nt) {
                const int col = nt * 8 + (lid & 3) * 2;
                *(float2*)(sOut + r0 * SOUTS + col) =
                    make_float2(acc[mt][nt][0], acc[mt][nt][1]);
                *(float2*)(sOut + (r0 + 8) * SOUTS + col) =
                    make_float2(acc[mt][nt][2], acc[mt][nt][3]);
            }
        }
    }
    __syncthreads();

    // ---- coalesced epilogue ----
    {
        const float* sOut = (const float*)dsm;
        const float* sBase = (const float*)(dsm + PSB);
        const float* sWsep = (const float*)(dsm + PSW);
        const float* sSep  = (const float*)(dsm + PSS);
        const int f4 = tid & 15, h = tid >> 4;
        const int o4 = f4 * 4;
        float4 b4 = *(const float4*)(sBase + o4);
        float4 w4 = *(const float4*)(sWsep + o4);
        const bool peJ = (bt == 0) && (f4 >= 8);
        #pragma unroll
        for (int rr = 0; rr < 16; ++rr) {
            const int row = rr * 8 + h;
            const int j = j0 + row;
            float4 v = *(const float4*)(sOut + row * SOUTS + o4);
            float sep = sSep[row];
            float4 r4 = *(const float4*)(g_eR + ((size_t)(bt * Ld + j)) * Kd + o4);
            v.x += b4.x + r4.x + sep * w4.x;
            v.y += b4.y + r4.y + sep * w4.y;
            v.z += b4.z + r4.z + sep * w4.z;
            v.w += b4.w + r4.w + sep * w4.w;
            if (peJ) {
                float4 p4 = *(const float4*)(g_pe + j * 32 + (o4 - 32));
                v.x += p4.x; v.y += p4.y; v.z += p4.z; v.w += p4.w;
            }
            __stcs((float4*)(out + (rowbase + row) * Kd + o4), v);
        }
    }
}

// ---------------------------------------------------------------------------
extern "C" void kernel_launch(void* const* d_in, const int* in_sizes, int n_in,
                              void* d_out, int out_size) {
    const float* t1d = (const float*)d_in[0];
    const float* t2d = (const float*)d_in[1];
    const float* p1w = (const float*)d_in[2];
    const float* p1b = (const float*)d_in[3];
    const float* c1w = (const float*)d_in[4];
    const float* c2w = (const float*)d_in[5];
    const float* pw  = (const float*)d_in[6];
    const float* pb  = (const float*)d_in[7];
    float* out = (float*)d_out;
    (void)in_sizes; (void)n_in; (void)out_size;

    k_tower<<<128, 512>>>(t1d, p1w, p1b, c1w, c2w, pw, pb);
    k_pair<<<8192, 128, DSMEM>>>(t2d, pw, out);
}